// round 16
// baseline (speedup 1.0000x reference)
#include <cuda_runtime.h>
#include <cuda_bf16.h>
#include <cstdint>
#include <cstddef>

#define BZ   256
#define SEQ  512
#define INS  256
#define HID  256

// ---------------------------------------------------------------------------
// generic helpers
// ---------------------------------------------------------------------------
__device__ __forceinline__ void ffma2(unsigned long long &acc,
                                      unsigned long long a,
                                      unsigned long long b) {
    asm volatile("fma.rn.f32x2 %0, %1, %2, %0;" : "+l"(acc) : "l"(a), "l"(b));
}
__device__ __forceinline__ unsigned long long pack2(float x, float y) {
    unsigned long long r;
    asm("mov.b64 %0, {%1, %2};" : "=l"(r) : "f"(x), "f"(y));
    return r;
}
__device__ __forceinline__ float2 unpack2(unsigned long long v) {
    float2 f;
    asm("mov.b64 {%0, %1}, %2;" : "=f"(f.x), "=f"(f.y) : "l"(v));
    return f;
}
__device__ __forceinline__ float acc_sum(unsigned long long v) {
    float2 p = unpack2(v);
    return p.x + p.y;
}
__device__ __forceinline__ float tanh_fast(float x) {
    float e;
    asm("ex2.approx.f32 %0, %1;" : "=f"(e) : "f"(x * 2.8853900817779268f));
    float r;
    asm("rcp.approx.f32 %0, %1;" : "=f"(r) : "f"(e + 1.0f));
    return fmaf(-2.0f, r, 1.0f);
}
__device__ __forceinline__ void bar_named(int id, int nthreads) {
    asm volatile("bar.sync %0, %1;" :: "r"(id), "r"(nthreads) : "memory");
}

// warp-level bf16 MMA (baseline PTX, sm_80+; works on plain sm_103 target)
__device__ __forceinline__ void mma_bf16(float* c, const unsigned* a,
                                         const unsigned* b) {
    asm volatile(
        "mma.sync.aligned.m16n8k16.row.col.f32.bf16.bf16.f32 "
        "{%0,%1,%2,%3}, {%4,%5,%6,%7}, {%8,%9}, {%0,%1,%2,%3};\n"
        : "+f"(c[0]), "+f"(c[1]), "+f"(c[2]), "+f"(c[3])
        : "r"(a[0]), "r"(a[1]), "r"(a[2]), "r"(a[3]), "r"(b[0]), "r"(b[1]));
}

// split two fp32 into packed bf16 hi pair + bf16 lo pair (lo = exact residual)
__device__ __forceinline__ void split2(float x, float y,
                                       unsigned &hi, unsigned &lo) {
    __nv_bfloat16 hx = __float2bfloat16_rn(x);
    __nv_bfloat16 hy = __float2bfloat16_rn(y);
    float lx = x - __bfloat162float(hx);
    float ly = y - __bfloat162float(hy);
    hi = (unsigned)__bfloat16_as_ushort(hx)
       | ((unsigned)__bfloat16_as_ushort(hy) << 16);
    asm("cvt.rn.bf16x2.f32 %0, %1, %2;" : "=r"(lo) : "f"(ly), "f"(lx));
}

// ---------------------------------------------------------------------------
// U prep: split U into bf16 hi/lo, transposed to [n][k] (MMA B is col-major k)
// ---------------------------------------------------------------------------
__device__ __nv_bfloat16 g_Uhi[256 * 256];
__device__ __nv_bfloat16 g_Ulo[256 * 256];

__global__ void uprep_kernel(const float* __restrict__ U) {
    int k = blockIdx.x;
    int n = threadIdx.x;
    float v = U[k * 256 + n];
    __nv_bfloat16 hi = __float2bfloat16_rn(v);
    float lo = v - __bfloat162float(hi);
    g_Uhi[n * 256 + k] = hi;
    g_Ulo[n * 256 + k] = __float2bfloat16_rn(lo);
}

// ---------------------------------------------------------------------------
// Kernel 1: XU = X @ U + bias via warp-MMA bf16 hi/lo split (3 products).
// Persistent CTAs, grid 296. R15 BUG FIXED: total tiles = 1024 m-tiles x 2
// n-halves = 2048 (was 1024 -> half of M never computed, rel_err 0.71).
// Tile math/compute identical to the R14 winner.
// ---------------------------------------------------------------------------
#define APITCH 72
#define XA_HI 0
#define XA_LO 18432
#define XB_HI 36864
#define XB_LO 55296
#define XU_SMEM 73728
#define XU_GRID 296
#define XU_TILES 2048            // 1024 m-tiles x 2 n-halves

__global__ void __launch_bounds__(256, 2)
xu_mma_kernel(const float* __restrict__ X, const float* __restrict__ bias,
              float* __restrict__ C)
{
    extern __shared__ __align__(16) char smem[];
    __nv_bfloat16* Ahi = (__nv_bfloat16*)(smem + XA_HI);
    __nv_bfloat16* Alo = (__nv_bfloat16*)(smem + XA_LO);
    __nv_bfloat16* Bhi = (__nv_bfloat16*)(smem + XB_HI);
    __nv_bfloat16* Blo = (__nv_bfloat16*)(smem + XB_LO);

    const int tid  = threadIdx.x;
    const int lane = tid & 31;
    const int wid  = tid >> 5;
    const int wm   = wid & 1;          // m half (64 rows)
    const int wn   = wid >> 1;         // n quarter (32 cols)

    const int lr = tid >> 1;           // 0..127: tile row for loads
    const int kh = (tid & 1) * 32;     // k-half within 64-chunk
    const int qr = lane >> 2;          // 0..7
    const int kq = (lane & 3) * 2;     // 0,2,4,6
    const int qc = (lane & 3) * 2;

    for (int tile = blockIdx.x; tile < XU_TILES; tile += XU_GRID) {
        const int m_base = (tile >> 1) * 128;
        const int n_base = (tile & 1) * 128;

        float acc[4][4][4];
#pragma unroll
        for (int mi = 0; mi < 4; mi++)
#pragma unroll
            for (int nj = 0; nj < 4; nj++)
#pragma unroll
                for (int q = 0; q < 4; q++) acc[mi][nj][q] = 0.f;

        for (int kc = 0; kc < 4; kc++) {
            // ---- A tile: X[m_base+lr][kc*64+kh .. +32] fp32 -> bf16 hi/lo
            {
                const float4* xs = (const float4*)
                    (X + (size_t)(m_base + lr) * 256 + kc * 64 + kh);
                __nv_bfloat16* ah = Ahi + lr * APITCH + kh;
                __nv_bfloat16* al = Alo + lr * APITCH + kh;
#pragma unroll
                for (int i = 0; i < 8; i++) {
                    float4 v = xs[i];
                    unsigned h01, l01, h23, l23;
                    split2(v.x, v.y, h01, l01);
                    split2(v.z, v.w, h23, l23);
                    *(unsigned long long*)(ah + i * 4) =
                        (unsigned long long)h01 | ((unsigned long long)h23 << 32);
                    *(unsigned long long*)(al + i * 4) =
                        (unsigned long long)l01 | ((unsigned long long)l23 << 32);
                }
            }
            // ---- B tile: g_U{hi,lo}[n_base+lr][kc*64+kh .. +32] copy
            {
                const uint4* bh = (const uint4*)
                    (g_Uhi + (size_t)(n_base + lr) * 256 + kc * 64 + kh);
                const uint4* bl = (const uint4*)
                    (g_Ulo + (size_t)(n_base + lr) * 256 + kc * 64 + kh);
                uint4* dh = (uint4*)(Bhi + lr * APITCH + kh);
                uint4* dl = (uint4*)(Blo + lr * APITCH + kh);
#pragma unroll
                for (int i = 0; i < 4; i++) { dh[i] = bh[i]; dl[i] = bl[i]; }
            }
            __syncthreads();

            // ---- compute: 4 k16-steps
#pragma unroll
            for (int ks = 0; ks < 4; ks++) {
                const int k0 = ks * 16 + kq;
                unsigned a_hi[4][4], a_lo[4][4];
#pragma unroll
                for (int mi = 0; mi < 4; mi++) {
                    const int ra = (wm * 64 + mi * 16 + qr) * APITCH + k0;
                    a_hi[mi][0] = *(const unsigned*)&Ahi[ra];
                    a_hi[mi][1] = *(const unsigned*)&Ahi[ra + 8 * APITCH];
                    a_hi[mi][2] = *(const unsigned*)&Ahi[ra + 8];
                    a_hi[mi][3] = *(const unsigned*)&Ahi[ra + 8 * APITCH + 8];
                    a_lo[mi][0] = *(const unsigned*)&Alo[ra];
                    a_lo[mi][1] = *(const unsigned*)&Alo[ra + 8 * APITCH];
                    a_lo[mi][2] = *(const unsigned*)&Alo[ra + 8];
                    a_lo[mi][3] = *(const unsigned*)&Alo[ra + 8 * APITCH + 8];
                }
#pragma unroll
                for (int nj = 0; nj < 4; nj++) {
                    const int rb = (wn * 32 + nj * 8 + qr) * APITCH + k0;
                    unsigned b_hi[2], b_lo[2];
                    b_hi[0] = *(const unsigned*)&Bhi[rb];
                    b_hi[1] = *(const unsigned*)&Bhi[rb + 8];
                    b_lo[0] = *(const unsigned*)&Blo[rb];
                    b_lo[1] = *(const unsigned*)&Blo[rb + 8];
#pragma unroll
                    for (int mi = 0; mi < 4; mi++) {
                        mma_bf16(acc[mi][nj], a_hi[mi], b_hi);
                        mma_bf16(acc[mi][nj], a_lo[mi], b_hi);
                        mma_bf16(acc[mi][nj], a_hi[mi], b_lo);
                    }
                }
            }
            __syncthreads();
        }

        // ---- epilogue: add bias, store (fragment layout m16n8: quads)
#pragma unroll
        for (int mi = 0; mi < 4; mi++) {
            const int row0 = m_base + wm * 64 + mi * 16 + qr;
#pragma unroll
            for (int nj = 0; nj < 4; nj++) {
                const int col = n_base + wn * 32 + nj * 8 + qc;
                float2 b2 = *(const float2*)(bias + col);
                float2 o0 = { acc[mi][nj][0] + b2.x, acc[mi][nj][1] + b2.y };
                float2 o1 = { acc[mi][nj][2] + b2.x, acc[mi][nj][3] + b2.y };
                *(float2*)(C + (size_t)row0 * 256 + col) = o0;
                *(float2*)(C + (size_t)(row0 + 8) * 256 + col) = o1;
            }
        }
        __syncthreads();   // smem tiles reused by next persistent tile
    }
}

// ---------------------------------------------------------------------------
// Kernel 2: EXACT champion rnn (measured 582us) — do not touch.
// ---------------------------------------------------------------------------
#define KREG 20
#define KSM  12
#define VSM_U64S   (8 * (KSM/2) * 256)
#define RED_HALF   (8 * 2 * 256)
#define RED_FLOATS (2 * RED_HALF)
#define HB_FLOATS  (2 * 2 * 256)
#define RNN_SMEM_BYTES (VSM_U64S * 8 + (RED_FLOATS + HB_FLOATS) * 4)

__global__ void __launch_bounds__(512, 1)
rnn_kernel(const float* __restrict__ enc, const float* __restrict__ V,
           float* __restrict__ dec, float* __restrict__ outenc)
{
    extern __shared__ __align__(16) unsigned long long smem_u64[];
    unsigned long long* Vsm = smem_u64;
    float* red = (float*)(smem_u64 + VSM_U64S);
    float* hb  = red + RED_FLOATS;

    const int tid = threadIdx.x;
    const int l   = tid & 31;
    const int w   = tid >> 5;
    const int kw  = w & 7;
    const int cw  = w >> 3;
    const int b0  = blockIdx.x * 2;
    const int K   = kw * 32;
    const int col = cw * 128 + l;

    unsigned long long Vr[4][KREG / 2];
#pragma unroll
    for (int cc = 0; cc < 4; cc++) {
        const float* Vc = V + (size_t)K * HID + col + 32 * cc;
#pragma unroll
        for (int j = 0; j < KREG / 2; j++)
            Vr[cc][j] = pack2(Vc[(size_t)(2 * j) * HID],
                              Vc[(size_t)(2 * j + 1) * HID]);
    }
    for (int idx = tid; idx < VSM_U64S; idx += 512) {
        int kk  = idx >> 8;
        int c   = idx & 255;
        int kw2 = kk / (KSM / 2);
        int j   = kk % (KSM / 2);
        int k   = kw2 * 32 + KREG + 2 * j;
        Vsm[idx] = pack2(V[(size_t)k * HID + c], V[(size_t)(k + 1) * HID + c]);
    }
    {
        const float ev = enc[(size_t)b0 * HID + tid];
        hb[tid] = ev;
        outenc[(size_t)b0 * HID + tid] = ev;
    }
    __syncthreads();

    const int fr = tid >> 8;
    const int fc = tid & 255;
    const size_t oBase = ((size_t)(b0 + fr) * SEQ) * HID + fc;

    const int rstore = kw * 512 + cw * 128 + l;
    const int barid  = 1 + kw;
    int cur = 0;

#pragma unroll 1
    for (int t = 0; t < SEQ; t++) {
        const float xu = dec[oBase + (size_t)t * HID];

        float* redb = red + (t & 1) * RED_HALF;
        const float* h0p = hb + cur * 512 + K;
        const float* h1p = h0p + 256;

        unsigned long long acc[2][4];
#pragma unroll
        for (int r = 0; r < 2; r++)
#pragma unroll
            for (int cc = 0; cc < 4; cc++) acc[r][cc] = 0ULL;

        const unsigned long long* vsb = Vsm + kw * ((KSM / 2) * 256) + col;
#pragma unroll
        for (int i = 0; i < KSM / 4; i++) {
            ulonglong2 h0 = *(const ulonglong2*)(h0p + KREG + 4 * i);
            ulonglong2 h1 = *(const ulonglong2*)(h1p + KREG + 4 * i);
#pragma unroll
            for (int cc = 0; cc < 4; cc++) {
                unsigned long long v0 = vsb[(2 * i) * 256 + 32 * cc];
                unsigned long long v1 = vsb[(2 * i + 1) * 256 + 32 * cc];
                ffma2(acc[0][cc], h0.x, v0);
                ffma2(acc[0][cc], h0.y, v1);
                ffma2(acc[1][cc], h1.x, v0);
                ffma2(acc[1][cc], h1.y, v1);
            }
        }
#pragma unroll
        for (int i = 0; i < KREG / 4; i++) {
            ulonglong2 h0 = *(const ulonglong2*)(h0p + 4 * i);
            ulonglong2 h1 = *(const ulonglong2*)(h1p + 4 * i);
#pragma unroll
            for (int cc = 0; cc < 4; cc++) {
                ffma2(acc[0][cc], h0.x, Vr[cc][2 * i]);
                ffma2(acc[0][cc], h0.y, Vr[cc][2 * i + 1]);
                ffma2(acc[1][cc], h1.x, Vr[cc][2 * i]);
                ffma2(acc[1][cc], h1.y, Vr[cc][2 * i + 1]);
            }
        }

#pragma unroll
        for (int r = 0; r < 2; r++)
#pragma unroll
            for (int cc = 0; cc < 4; cc++)
                redb[rstore + r * 256 + 32 * cc] = acc_sum(acc[r][cc]);
        __syncthreads();

        float s = 0.f;
#pragma unroll
        for (int ww = 0; ww < 8; ww++)
            s += redb[ww * 512 + fr * 256 + fc];
        const float v = tanh_fast(s + xu);

        dec[oBase + (size_t)t * HID] = v;

        const int nxt = cur ^ 1;
        hb[nxt * 512 + fr * 256 + fc] = v;
        bar_named(barid, 64);
        cur = nxt;
    }
}

// ---------------------------------------------------------------------------
// launch
// ---------------------------------------------------------------------------
extern "C" void kernel_launch(void* const* d_in, const int* in_sizes, int n_in,
                              void* d_out, int out_size)
{
    const float* enc  = (const float*)d_in[0];
    const float* xdec = (const float*)d_in[1];
    const float* U    = (const float*)d_in[2];
    const float* V    = (const float*)d_in[3];
    const float* b    = (const float*)d_in[4];

    float* out = (float*)d_out;
    float* dec = out + (size_t)BZ * HID;

    uprep_kernel<<<256, 256>>>(U);

    cudaFuncSetAttribute(xu_mma_kernel,
                         cudaFuncAttributeMaxDynamicSharedMemorySize, XU_SMEM);
    xu_mma_kernel<<<XU_GRID, 256, XU_SMEM>>>(xdec, b, dec);

    cudaFuncSetAttribute(rnn_kernel,
                         cudaFuncAttributeMaxDynamicSharedMemorySize,
                         RNN_SMEM_BYTES);
    rnn_kernel<<<128, 512, RNN_SMEM_BYTES>>>(enc, V, dec, out);
}

// round 17
// speedup vs baseline: 1.0170x; 1.0170x over previous
#include <cuda_runtime.h>
#include <cuda_bf16.h>
#include <cstdint>
#include <cstddef>

#define BZ   256
#define SEQ  512
#define INS  256
#define HID  256

// ---------------------------------------------------------------------------
// generic helpers
// ---------------------------------------------------------------------------
__device__ __forceinline__ void ffma2(unsigned long long &acc,
                                      unsigned long long a,
                                      unsigned long long b) {
    asm volatile("fma.rn.f32x2 %0, %1, %2, %0;" : "+l"(acc) : "l"(a), "l"(b));
}
__device__ __forceinline__ unsigned long long pack2(float x, float y) {
    unsigned long long r;
    asm("mov.b64 %0, {%1, %2};" : "=l"(r) : "f"(x), "f"(y));
    return r;
}
__device__ __forceinline__ float2 unpack2(unsigned long long v) {
    float2 f;
    asm("mov.b64 {%0, %1}, %2;" : "=f"(f.x), "=f"(f.y) : "l"(v));
    return f;
}
__device__ __forceinline__ float acc_sum(unsigned long long v) {
    float2 p = unpack2(v);
    return p.x + p.y;
}
__device__ __forceinline__ float tanh_fast(float x) {
    float e;
    asm("ex2.approx.f32 %0, %1;" : "=f"(e) : "f"(x * 2.8853900817779268f));
    float r;
    asm("rcp.approx.f32 %0, %1;" : "=f"(r) : "f"(e + 1.0f));
    return fmaf(-2.0f, r, 1.0f);
}
__device__ __forceinline__ void bar_named(int id, int nthreads) {
    asm volatile("bar.sync %0, %1;" :: "r"(id), "r"(nthreads) : "memory");
}

// warp-level bf16 MMA (baseline PTX, sm_80+; works on plain sm_103 target)
__device__ __forceinline__ void mma_bf16(float* c, const unsigned* a,
                                         const unsigned* b) {
    asm volatile(
        "mma.sync.aligned.m16n8k16.row.col.f32.bf16.bf16.f32 "
        "{%0,%1,%2,%3}, {%4,%5,%6,%7}, {%8,%9}, {%0,%1,%2,%3};\n"
        : "+f"(c[0]), "+f"(c[1]), "+f"(c[2]), "+f"(c[3])
        : "r"(a[0]), "r"(a[1]), "r"(a[2]), "r"(a[3]), "r"(b[0]), "r"(b[1]));
}

// split two fp32 into packed bf16 hi pair + bf16 lo pair (lo = exact residual)
__device__ __forceinline__ void split2(float x, float y,
                                       unsigned &hi, unsigned &lo) {
    __nv_bfloat16 hx = __float2bfloat16_rn(x);
    __nv_bfloat16 hy = __float2bfloat16_rn(y);
    float lx = x - __bfloat162float(hx);
    float ly = y - __bfloat162float(hy);
    hi = (unsigned)__bfloat16_as_ushort(hx)
       | ((unsigned)__bfloat16_as_ushort(hy) << 16);
    asm("cvt.rn.bf16x2.f32 %0, %1, %2;" : "=r"(lo) : "f"(ly), "f"(lx));
}

// ---------------------------------------------------------------------------
// U prep: split U into bf16 hi/lo, transposed to [n][k].
// v2: smem-tile transpose (33-pitch, conflict-free) -> coalesced 64B bf16
// writes instead of 2B/lane scattered stores. Isolated kernel; worst case
// neutral.
// ---------------------------------------------------------------------------
__device__ __nv_bfloat16 g_Uhi[256 * 256];
__device__ __nv_bfloat16 g_Ulo[256 * 256];

__global__ void uprep_kernel(const float* __restrict__ U) {
    __shared__ float sh[32][33];
    const int kt = blockIdx.x * 32;
    const int nt = blockIdx.y * 32;
    const int tx = threadIdx.x;          // 0..31
    const int ty = threadIdx.y;          // 0..7

#pragma unroll
    for (int i = 0; i < 4; i++)
        sh[ty + 8 * i][tx] = U[(size_t)(kt + ty + 8 * i) * 256 + nt + tx];
    __syncthreads();

#pragma unroll
    for (int i = 0; i < 4; i++) {
        const int n = nt + ty + 8 * i;
        const float v = sh[tx][ty + 8 * i];          // k = kt + tx
        __nv_bfloat16 hi = __float2bfloat16_rn(v);
        float lo = v - __bfloat162float(hi);
        g_Uhi[(size_t)n * 256 + kt + tx] = hi;       // coalesced 64B/warp
        g_Ulo[(size_t)n * 256 + kt + tx] = __float2bfloat16_rn(lo);
    }
}

// ---------------------------------------------------------------------------
// Kernel 1: XU = X @ U + bias via warp-MMA bf16 hi/lo split (3 products,
// lo*lo dropped -> rel err ~4e-6 end to end). EXACT R14 champion version:
// grid dim3(1024, 2), CTA 256 thr, tile 128m x 128n, K chunks of 64.
// [R15/16 persistent-CTA variant regressed +13.5us: reverted.]
// ---------------------------------------------------------------------------
#define APITCH 72
#define XA_HI 0
#define XA_LO 18432
#define XB_HI 36864
#define XB_LO 55296
#define XU_SMEM 73728

__global__ void __launch_bounds__(256, 2)
xu_mma_kernel(const float* __restrict__ X, const float* __restrict__ bias,
              float* __restrict__ C)
{
    extern __shared__ __align__(16) char smem[];
    __nv_bfloat16* Ahi = (__nv_bfloat16*)(smem + XA_HI);
    __nv_bfloat16* Alo = (__nv_bfloat16*)(smem + XA_LO);
    __nv_bfloat16* Bhi = (__nv_bfloat16*)(smem + XB_HI);
    __nv_bfloat16* Blo = (__nv_bfloat16*)(smem + XB_LO);

    const int tid  = threadIdx.x;
    const int lane = tid & 31;
    const int wid  = tid >> 5;
    const int wm   = wid & 1;          // m half (64 rows)
    const int wn   = wid >> 1;         // n quarter (32 cols)
    const int m_base = blockIdx.x * 128;
    const int n_base = blockIdx.y * 128;

    float acc[4][4][4];
#pragma unroll
    for (int mi = 0; mi < 4; mi++)
#pragma unroll
        for (int nj = 0; nj < 4; nj++)
#pragma unroll
            for (int q = 0; q < 4; q++) acc[mi][nj][q] = 0.f;

    const int lr = tid >> 1;           // 0..127: tile row for loads
    const int kh = (tid & 1) * 32;     // k-half within 64-chunk

    for (int kc = 0; kc < 4; kc++) {
        // ---- A tile: X[m_base+lr][kc*64+kh .. +32] fp32 -> bf16 hi/lo
        {
            const float4* xs = (const float4*)
                (X + (size_t)(m_base + lr) * 256 + kc * 64 + kh);
            __nv_bfloat16* ah = Ahi + lr * APITCH + kh;
            __nv_bfloat16* al = Alo + lr * APITCH + kh;
#pragma unroll
            for (int i = 0; i < 8; i++) {
                float4 v = xs[i];
                unsigned h01, l01, h23, l23;
                split2(v.x, v.y, h01, l01);
                split2(v.z, v.w, h23, l23);
                *(unsigned long long*)(ah + i * 4) =
                    (unsigned long long)h01 | ((unsigned long long)h23 << 32);
                *(unsigned long long*)(al + i * 4) =
                    (unsigned long long)l01 | ((unsigned long long)l23 << 32);
            }
        }
        // ---- B tile: g_U{hi,lo}[n_base+lr][kc*64+kh .. +32] copy
        {
            const uint4* bh = (const uint4*)
                (g_Uhi + (size_t)(n_base + lr) * 256 + kc * 64 + kh);
            const uint4* bl = (const uint4*)
                (g_Ulo + (size_t)(n_base + lr) * 256 + kc * 64 + kh);
            uint4* dh = (uint4*)(Bhi + lr * APITCH + kh);
            uint4* dl = (uint4*)(Blo + lr * APITCH + kh);
#pragma unroll
            for (int i = 0; i < 4; i++) { dh[i] = bh[i]; dl[i] = bl[i]; }
        }
        __syncthreads();

        // ---- compute: 4 k16-steps
        const int qr = lane >> 2;          // 0..7
        const int kq = (lane & 3) * 2;     // 0,2,4,6
#pragma unroll
        for (int ks = 0; ks < 4; ks++) {
            const int k0 = ks * 16 + kq;
            unsigned a_hi[4][4], a_lo[4][4];
#pragma unroll
            for (int mi = 0; mi < 4; mi++) {
                const int ra = (wm * 64 + mi * 16 + qr) * APITCH + k0;
                a_hi[mi][0] = *(const unsigned*)&Ahi[ra];
                a_hi[mi][1] = *(const unsigned*)&Ahi[ra + 8 * APITCH];
                a_hi[mi][2] = *(const unsigned*)&Ahi[ra + 8];
                a_hi[mi][3] = *(const unsigned*)&Ahi[ra + 8 * APITCH + 8];
                a_lo[mi][0] = *(const unsigned*)&Alo[ra];
                a_lo[mi][1] = *(const unsigned*)&Alo[ra + 8 * APITCH];
                a_lo[mi][2] = *(const unsigned*)&Alo[ra + 8];
                a_lo[mi][3] = *(const unsigned*)&Alo[ra + 8 * APITCH + 8];
            }
#pragma unroll
            for (int nj = 0; nj < 4; nj++) {
                const int rb = (wn * 32 + nj * 8 + qr) * APITCH + k0;
                unsigned b_hi[2], b_lo[2];
                b_hi[0] = *(const unsigned*)&Bhi[rb];
                b_hi[1] = *(const unsigned*)&Bhi[rb + 8];
                b_lo[0] = *(const unsigned*)&Blo[rb];
                b_lo[1] = *(const unsigned*)&Blo[rb + 8];
#pragma unroll
                for (int mi = 0; mi < 4; mi++) {
                    mma_bf16(acc[mi][nj], a_hi[mi], b_hi);
                    mma_bf16(acc[mi][nj], a_lo[mi], b_hi);
                    mma_bf16(acc[mi][nj], a_hi[mi], b_lo);
                }
            }
        }
        __syncthreads();
    }

    // ---- epilogue: add bias, store (fragment layout m16n8: quads)
    const int qr = lane >> 2;
    const int qc = (lane & 3) * 2;
#pragma unroll
    for (int mi = 0; mi < 4; mi++) {
        const int row0 = m_base + wm * 64 + mi * 16 + qr;
#pragma unroll
        for (int nj = 0; nj < 4; nj++) {
            const int col = n_base + wn * 32 + nj * 8 + qc;
            float2 b2 = *(const float2*)(bias + col);
            float2 o0 = { acc[mi][nj][0] + b2.x, acc[mi][nj][1] + b2.y };
            float2 o1 = { acc[mi][nj][2] + b2.x, acc[mi][nj][3] + b2.y };
            *(float2*)(C + (size_t)row0 * 256 + col) = o0;
            *(float2*)(C + (size_t)(row0 + 8) * 256 + col) = o1;
        }
    }
}

// ---------------------------------------------------------------------------
// Kernel 2: EXACT champion rnn (measured 582us, stable across rounds) —
// do not touch.
// ---------------------------------------------------------------------------
#define KREG 20
#define KSM  12
#define VSM_U64S   (8 * (KSM/2) * 256)
#define RED_HALF   (8 * 2 * 256)
#define RED_FLOATS (2 * RED_HALF)
#define HB_FLOATS  (2 * 2 * 256)
#define RNN_SMEM_BYTES (VSM_U64S * 8 + (RED_FLOATS + HB_FLOATS) * 4)

__global__ void __launch_bounds__(512, 1)
rnn_kernel(const float* __restrict__ enc, const float* __restrict__ V,
           float* __restrict__ dec, float* __restrict__ outenc)
{
    extern __shared__ __align__(16) unsigned long long smem_u64[];
    unsigned long long* Vsm = smem_u64;
    float* red = (float*)(smem_u64 + VSM_U64S);
    float* hb  = red + RED_FLOATS;

    const int tid = threadIdx.x;
    const int l   = tid & 31;
    const int w   = tid >> 5;
    const int kw  = w & 7;
    const int cw  = w >> 3;
    const int b0  = blockIdx.x * 2;
    const int K   = kw * 32;
    const int col = cw * 128 + l;

    unsigned long long Vr[4][KREG / 2];
#pragma unroll
    for (int cc = 0; cc < 4; cc++) {
        const float* Vc = V + (size_t)K * HID + col + 32 * cc;
#pragma unroll
        for (int j = 0; j < KREG / 2; j++)
            Vr[cc][j] = pack2(Vc[(size_t)(2 * j) * HID],
                              Vc[(size_t)(2 * j + 1) * HID]);
    }
    for (int idx = tid; idx < VSM_U64S; idx += 512) {
        int kk  = idx >> 8;
        int c   = idx & 255;
        int kw2 = kk / (KSM / 2);
        int j   = kk % (KSM / 2);
        int k   = kw2 * 32 + KREG + 2 * j;
        Vsm[idx] = pack2(V[(size_t)k * HID + c], V[(size_t)(k + 1) * HID + c]);
    }
    {
        const float ev = enc[(size_t)b0 * HID + tid];
        hb[tid] = ev;
        outenc[(size_t)b0 * HID + tid] = ev;
    }
    __syncthreads();

    const int fr = tid >> 8;
    const int fc = tid & 255;
    const size_t oBase = ((size_t)(b0 + fr) * SEQ) * HID + fc;

    const int rstore = kw * 512 + cw * 128 + l;
    const int barid  = 1 + kw;
    int cur = 0;

#pragma unroll 1
    for (int t = 0; t < SEQ; t++) {
        const float xu = dec[oBase + (size_t)t * HID];

        float* redb = red + (t & 1) * RED_HALF;
        const float* h0p = hb + cur * 512 + K;
        const float* h1p = h0p + 256;

        unsigned long long acc[2][4];
#pragma unroll
        for (int r = 0; r < 2; r++)
#pragma unroll
            for (int cc = 0; cc < 4; cc++) acc[r][cc] = 0ULL;

        const unsigned long long* vsb = Vsm + kw * ((KSM / 2) * 256) + col;
#pragma unroll
        for (int i = 0; i < KSM / 4; i++) {
            ulonglong2 h0 = *(const ulonglong2*)(h0p + KREG + 4 * i);
            ulonglong2 h1 = *(const ulonglong2*)(h1p + KREG + 4 * i);
#pragma unroll
            for (int cc = 0; cc < 4; cc++) {
                unsigned long long v0 = vsb[(2 * i) * 256 + 32 * cc];
                unsigned long long v1 = vsb[(2 * i + 1) * 256 + 32 * cc];
                ffma2(acc[0][cc], h0.x, v0);
                ffma2(acc[0][cc], h0.y, v1);
                ffma2(acc[1][cc], h1.x, v0);
                ffma2(acc[1][cc], h1.y, v1);
            }
        }
#pragma unroll
        for (int i = 0; i < KREG / 4; i++) {
            ulonglong2 h0 = *(const ulonglong2*)(h0p + 4 * i);
            ulonglong2 h1 = *(const ulonglong2*)(h1p + 4 * i);
#pragma unroll
            for (int cc = 0; cc < 4; cc++) {
                ffma2(acc[0][cc], h0.x, Vr[cc][2 * i]);
                ffma2(acc[0][cc], h0.y, Vr[cc][2 * i + 1]);
                ffma2(acc[1][cc], h1.x, Vr[cc][2 * i]);
                ffma2(acc[1][cc], h1.y, Vr[cc][2 * i + 1]);
            }
        }

#pragma unroll
        for (int r = 0; r < 2; r++)
#pragma unroll
            for (int cc = 0; cc < 4; cc++)
                redb[rstore + r * 256 + 32 * cc] = acc_sum(acc[r][cc]);
        __syncthreads();

        float s = 0.f;
#pragma unroll
        for (int ww = 0; ww < 8; ww++)
            s += redb[ww * 512 + fr * 256 + fc];
        const float v = tanh_fast(s + xu);

        dec[oBase + (size_t)t * HID] = v;

        const int nxt = cur ^ 1;
        hb[nxt * 512 + fr * 256 + fc] = v;
        bar_named(barid, 64);
        cur = nxt;
    }
}

// ---------------------------------------------------------------------------
// launch
// ---------------------------------------------------------------------------
extern "C" void kernel_launch(void* const* d_in, const int* in_sizes, int n_in,
                              void* d_out, int out_size)
{
    const float* enc  = (const float*)d_in[0];
    const float* xdec = (const float*)d_in[1];
    const float* U    = (const float*)d_in[2];
    const float* V    = (const float*)d_in[3];
    const float* b    = (const float*)d_in[4];

    float* out = (float*)d_out;
    float* dec = out + (size_t)BZ * HID;

    uprep_kernel<<<dim3(8, 8), dim3(32, 8)>>>(U);

    cudaFuncSetAttribute(xu_mma_kernel,
                         cudaFuncAttributeMaxDynamicSharedMemorySize, XU_SMEM);
    xu_mma_kernel<<<dim3((BZ * SEQ) / 128, HID / 128), 256, XU_SMEM>>>(
        xdec, b, dec);

    cudaFuncSetAttribute(rnn_kernel,
                         cudaFuncAttributeMaxDynamicSharedMemorySize,
                         RNN_SMEM_BYTES);
    rnn_kernel<<<128, 512, RNN_SMEM_BYTES>>>(enc, V, dec, out);
}